// round 3
// baseline (speedup 1.0000x reference)
#include <cuda_runtime.h>
#include <math.h>

#define DIM   128
#define KC    8
#define NMAX  50000
#define EMAX  1600000
#define XCAP  80           // max edges cached in SMEM per row

// Static scratch (no allocations allowed). 256B-aligned: we use 128-bit
// vector accesses on g_xn and alignment of __device__ arrays is otherwise
// only guaranteed to the element size.
__device__ __align__(256) float g_xn[(size_t)NMAX * DIM];   // normalized x (25.6 MB)
__device__ __align__(256) float g_pbuf[(size_t)EMAX * KC];  // fallback p scratch
__device__ int g_rs[NMAX + 1];                              // row CSR offsets

// ---------------------------------------------------------------------------
// Kernel 1: per-capsule L2 normalize x -> g_xn. One thread per capsule (16 f).
// ---------------------------------------------------------------------------
__global__ void knorm(const float* __restrict__ x, int ncap) {
    int i = blockIdx.x * blockDim.x + threadIdx.x;
    if (i >= ncap) return;
    const float4* src = ((const float4*)x) + (size_t)i * 4;
    float4 a = src[0], b = src[1], c = src[2], d = src[3];
    float s = a.x*a.x + a.y*a.y + a.z*a.z + a.w*a.w
            + b.x*b.x + b.y*b.y + b.z*b.z + b.w*b.w
            + c.x*c.x + c.y*c.y + c.z*c.z + c.w*c.w
            + d.x*d.x + d.y*d.y + d.z*d.z + d.w*d.w;
    float inv = 1.0f / fmaxf(sqrtf(s), 1e-12f);
    a.x*=inv; a.y*=inv; a.z*=inv; a.w*=inv;
    b.x*=inv; b.y*=inv; b.z*=inv; b.w*=inv;
    c.x*=inv; c.y*=inv; c.z*=inv; c.w*=inv;
    d.x*=inv; d.y*=inv; d.z*=inv; d.w*=inv;
    float4* dst = ((float4*)g_xn) + (size_t)i * 4;
    dst[0]=a; dst[1]=b; dst[2]=c; dst[3]=d;
}

// ---------------------------------------------------------------------------
// Kernel 2: CSR row offsets via binary search on sorted row_idx.
// ---------------------------------------------------------------------------
__global__ void krows(const int* __restrict__ row_idx, int n, int E) {
    int r = blockIdx.x * blockDim.x + threadIdx.x;
    if (r > n) return;
    if (r == n) { g_rs[n] = E; return; }
    int lo = 0, hi = E;
    while (lo < hi) {
        int mid = (lo + hi) >> 1;
        if (row_idx[mid] < r) lo = mid + 1; else hi = mid;
    }
    g_rs[r] = lo;
}

// ---------------------------------------------------------------------------
// Scatter-softmax over this row's p buffer (cnt edges x KC capsules).
// Thread t -> capsule k = t&7, strip j = t>>3 (0..15), stride 16 over edges.
// blend: p = 0.5*softmax(p) + 0.5*ppr  (fused into the normalize pass)
// ---------------------------------------------------------------------------
__device__ __forceinline__ void softmax_pass(
    float* __restrict__ p, int cnt,
    float* __restrict__ red, float* __restrict__ ms, float* __restrict__ ss,
    int t, const float* __restrict__ pprv, bool blend)
{
    const int k = t & 7, j = t >> 3;
    float pm = -1e30f;
    for (int e = j; e < cnt; e += 16) pm = fmaxf(pm, p[e*KC + k]);
    red[t] = pm;
    __syncthreads();
    if (t < KC) {
        float m = -1e30f;
        #pragma unroll
        for (int q = 0; q < 16; q++) m = fmaxf(m, red[q*KC + t]);
        ms[t] = m;
    }
    __syncthreads();
    float m = ms[k];
    float psum = 0.f;
    for (int e = j; e < cnt; e += 16) {
        float v = __expf(p[e*KC + k] - m);
        p[e*KC + k] = v;
        psum += v;
    }
    red[t] = psum;
    __syncthreads();
    if (t < KC) {
        float sv = 0.f;
        #pragma unroll
        for (int q = 0; q < 16; q++) sv += red[q*KC + t];
        ss[t] = sv;
    }
    __syncthreads();
    float sInv = 1.0f / fmaxf(ss[k], 1e-30f);
    if (blend) {
        for (int e = j; e < cnt; e += 16)
            p[e*KC + k] = 0.5f * p[e*KC + k] * sInv + 0.5f * pprv[e];
    } else {
        for (int e = j; e < cnt; e += 16)
            p[e*KC + k] = p[e*KC + k] * sInv;
    }
    __syncthreads();
}

// ---------------------------------------------------------------------------
// Per-row routing body. CACHED: x tile + p + ppr live in SMEM.
// Fallback (!CACHED): x gathered from L2 each pass, p in global scratch.
// ---------------------------------------------------------------------------
template<bool CACHED>
__device__ __forceinline__ void row_body(
    int r, int t, int s, int cnt,
    const float* __restrict__ pprg, const int* __restrict__ colg,
    float* __restrict__ out,
    float* __restrict__ x_sh, float* __restrict__ p_sh,
    float* __restrict__ ppr_sh,
    float* __restrict__ red, float* __restrict__ ms, float* __restrict__ ss)
{
    const unsigned FULL = 0xFFFFFFFFu;
    float* pbuf = CACHED ? p_sh : (g_pbuf + (size_t)s * KC);
    const float* pprv = CACHED ? ppr_sh : (pprg + s);
    const int cap = t >> 4;   // capsule owning dim t

    // u init: u[d] = sum_e xn[col[e]][d] * ppr[e]
    float u_d = 0.f;
    #pragma unroll 4
    for (int e = 0; e < cnt; e++) {
        float xv = CACHED ? x_sh[e*DIM + t]
                          : g_xn[(size_t)colg[s+e]*DIM + t];
        u_d += xv * pprv[e];
    }

    #pragma unroll
    for (int it = 0; it < 3; it++) {
        __syncthreads();   // pbuf about to be overwritten; prior reads done

        // Pass A: p[e][k] = <u capsule k, x_e capsule k>
        #pragma unroll 2
        for (int e = 0; e < cnt; e++) {
            float xv = CACHED ? x_sh[e*DIM + t]
                              : g_xn[(size_t)colg[s+e]*DIM + t];
            float v = u_d * xv;
            v += __shfl_xor_sync(FULL, v, 8);
            v += __shfl_xor_sync(FULL, v, 4);
            v += __shfl_xor_sync(FULL, v, 2);
            v += __shfl_xor_sync(FULL, v, 1);
            if ((t & 15) == 0) pbuf[e*KC + cap] = v;
        }
        __syncthreads();

        softmax_pass(pbuf, cnt, red, ms, ss, t, pprv, true);   // softmax + blend
        softmax_pass(pbuf, cnt, red, ms, ss, t, pprv, false);  // softmax

        // Pass B: u3[d] = sum_e x_e[d] * p[e][cap(d)]
        float acc = 0.f;
        #pragma unroll 4
        for (int e = 0; e < cnt; e++) {
            float xv = CACHED ? x_sh[e*DIM + t]
                              : g_xn[(size_t)colg[s+e]*DIM + t];
            acc += xv * pbuf[e*KC + cap];
        }

        if (it < 2) {
            float sq = acc * acc;
            sq += __shfl_xor_sync(FULL, sq, 8);
            sq += __shfl_xor_sync(FULL, sq, 4);
            sq += __shfl_xor_sync(FULL, sq, 2);
            sq += __shfl_xor_sync(FULL, sq, 1);
            u_d = acc / fmaxf(sqrtf(sq), 1e-12f);
        } else {
            out[(size_t)r * DIM + t] = acc;
        }
    }
}

// ---------------------------------------------------------------------------
// Kernel 3: one block (128 thr) per row; all 3 iterations fused.
// ---------------------------------------------------------------------------
__global__ void __launch_bounds__(128) kmain(
    const float* __restrict__ pprg,
    const int* __restrict__ colg,
    float* __restrict__ out, int E)
{
    extern __shared__ float smem[];
    float* x_sh   = smem;                       // XCAP*128
    float* p_sh   = x_sh + XCAP*DIM;            // XCAP*8
    float* ppr_sh = p_sh + XCAP*KC;             // XCAP
    int*   col_sh = (int*)(ppr_sh + XCAP);      // XCAP
    float* red    = (float*)(col_sh + XCAP);    // 128
    float* ms     = red + DIM;                  // 8
    float* ss     = ms + KC;                    // 8

    const int r = blockIdx.x;
    const int t = threadIdx.x;
    const int s = g_rs[r];
    int cnt = g_rs[r + 1] - s;
    cnt = max(0, min(cnt, E));                  // defensive clamp

    if (cnt <= XCAP) {
        for (int i = t; i < cnt; i += DIM) {
            col_sh[i] = colg[s + i];
            ppr_sh[i] = pprg[s + i];
        }
        __syncthreads();
        // stage x tile: one warp per edge (32 lanes x float4 = 512B)
        const int lane = t & 31, w = t >> 5;
        for (int e = w; e < cnt; e += 4) {
            const float4* src = (const float4*)(g_xn + (size_t)col_sh[e]*DIM);
            ((float4*)(x_sh + e*DIM))[lane] = src[lane];
        }
        __syncthreads();
        row_body<true>(r, t, s, cnt, pprg, colg, out,
                       x_sh, p_sh, ppr_sh, red, ms, ss);
    } else {
        row_body<false>(r, t, s, cnt, pprg, colg, out,
                        x_sh, p_sh, ppr_sh, red, ms, ss);
    }
}

// ---------------------------------------------------------------------------
extern "C" void kernel_launch(void* const* d_in, const int* in_sizes, int n_in,
                              void* d_out, int out_size)
{
    const float* x    = (const float*)d_in[0];   // (N,128) f32
    const float* ppr  = (const float*)d_in[1];   // (E,)    f32
    const int*   row  = (const int*)  d_in[2];   // (E,)    i32 sorted
    const int*   col  = (const int*)  d_in[3];   // (E,)    i32
    float* out = (float*)d_out;

    int n = in_sizes[0] / DIM;
    if (n > NMAX) n = NMAX;
    int E = in_sizes[1];
    if (E > EMAX) E = EMAX;
    if (n <= 0) return;

    const int ncap = n * KC;
    knorm<<<(ncap + 255) / 256, 256>>>(x, ncap);
    krows<<<(n + 1 + 255) / 256, 256>>>(row, n, E);

    const size_t SMEM = (size_t)(XCAP*DIM + XCAP*KC + XCAP + XCAP + DIM + 2*KC)
                        * sizeof(float);   // 45.2 KB
    cudaFuncSetAttribute(kmain, cudaFuncAttributeMaxDynamicSharedMemorySize,
                         (int)SMEM);
    kmain<<<n, 128, SMEM>>>(ppr, col, out, E);
}

// round 4
// speedup vs baseline: 1.8288x; 1.8288x over previous
#include <cuda_runtime.h>
#include <math.h>

#define DIM   128
#define KC    8
#define NMAX  50000
#define EMAX  1600000
#define XCAP  64            // max edges cached in SMEM per row
#define PSTR  (XCAP + 1)    // pbuf row stride (bank-conflict-free: 65 mod 32 = 1)
#define FULLM 0xFFFFFFFFu

__device__ __align__(256) float g_xn[(size_t)NMAX * DIM];   // normalized x (25.6 MB)
__device__ __align__(256) float g_pbuf[(size_t)EMAX * KC];  // fallback p scratch
__device__ int g_rs[NMAX + 1];                              // row CSR offsets

// ---------------------------------------------------------------------------
// Kernel 1: per-capsule L2 normalize x -> g_xn. One thread per capsule (16 f).
// ---------------------------------------------------------------------------
__global__ void knorm(const float* __restrict__ x, int ncap) {
    int i = blockIdx.x * blockDim.x + threadIdx.x;
    if (i >= ncap) return;
    const float4* src = ((const float4*)x) + (size_t)i * 4;
    float4 a = src[0], b = src[1], c = src[2], d = src[3];
    float s = a.x*a.x + a.y*a.y + a.z*a.z + a.w*a.w
            + b.x*b.x + b.y*b.y + b.z*b.z + b.w*b.w
            + c.x*c.x + c.y*c.y + c.z*c.z + c.w*c.w
            + d.x*d.x + d.y*d.y + d.z*d.z + d.w*d.w;
    float inv = 1.0f / fmaxf(sqrtf(s), 1e-12f);
    a.x*=inv; a.y*=inv; a.z*=inv; a.w*=inv;
    b.x*=inv; b.y*=inv; b.z*=inv; b.w*=inv;
    c.x*=inv; c.y*=inv; c.z*=inv; c.w*=inv;
    d.x*=inv; d.y*=inv; d.z*=inv; d.w*=inv;
    float4* dst = ((float4*)g_xn) + (size_t)i * 4;
    dst[0]=a; dst[1]=b; dst[2]=c; dst[3]=d;
}

// ---------------------------------------------------------------------------
// Kernel 2: CSR row offsets via binary search on sorted row_idx.
// ---------------------------------------------------------------------------
__global__ void krows(const int* __restrict__ row_idx, int n, int E) {
    int r = blockIdx.x * blockDim.x + threadIdx.x;
    if (r > n) return;
    if (r == n) { g_rs[n] = E; return; }
    int lo = 0, hi = E;
    while (lo < hi) {
        int mid = (lo + hi) >> 1;
        if (row_idx[mid] < r) lo = mid + 1; else hi = mid;
    }
    g_rs[r] = lo;
}

// ---------------------------------------------------------------------------
// Main kernel. One 128-thread block per row. Lane l of each warp owns dims
// [4l,4l+4) as a float4; every warp holds the full u in registers. Warp w
// processes edges e = w, w+4, ... Per-capsule softmax stats are reduced with
// in-warp shuffles over 16-thread groups (thread t -> capsule t>>4).
// ---------------------------------------------------------------------------
__global__ void __launch_bounds__(128) kmain(
    const float* __restrict__ pprg,
    const int* __restrict__ colg,
    float* __restrict__ out, int E)
{
    extern __shared__ float smem[];
    float4* x4_sh  = (float4*)smem;                  // XCAP*32 float4 (32 KB)
    float*  pbuf   = smem + XCAP*DIM;                // KC*PSTR
    float*  ppr_sh = pbuf + KC*PSTR;                 // XCAP
    int*    col_sh = (int*)(ppr_sh + XCAP);          // XCAP
    float4* red4   = (float4*)(col_sh + XCAP);       // 128 float4 (2 KB)
    float*  mred   = (float*)(red4 + DIM);           // 32
    float*  ssv    = mred + 32;                      // 8

    const int r = blockIdx.x;
    const int t = threadIdx.x;
    const int w = t >> 5, l = t & 31;
    const int cap = l >> 2;                // capsule owned by this lane's dims
    const int k16 = t >> 4, j16 = t & 15;  // softmax mapping: capsule, strip

    const int s = g_rs[r];
    int cnt = g_rs[r + 1] - s;
    cnt = max(0, min(cnt, E));

    const bool cached = (cnt <= XCAP);

    // ---- stage col/ppr, then x tile (fused with u-init accumulate) ----
    float4 u4 = make_float4(0.f, 0.f, 0.f, 0.f);
    if (cached) {
        for (int i = t; i < cnt; i += 128) {
            col_sh[i] = colg[s + i];
            ppr_sh[i] = pprg[s + i];
        }
        __syncthreads();
        for (int e = w; e < cnt; e += 4) {
            float4 xv = ((const float4*)(g_xn + (size_t)col_sh[e]*DIM))[l];
            x4_sh[e*32 + l] = xv;
            float pe = ppr_sh[e];
            u4.x += xv.x*pe; u4.y += xv.y*pe; u4.z += xv.z*pe; u4.w += xv.w*pe;
        }
    } else {
        for (int e = w; e < cnt; e += 4) {
            float4 xv = ((const float4*)(g_xn + (size_t)colg[s+e]*DIM))[l];
            float pe = pprg[s + e];
            u4.x += xv.x*pe; u4.y += xv.y*pe; u4.z += xv.z*pe; u4.w += xv.w*pe;
        }
    }
    // cross-warp reduce u (all warps end with identical full u)
    red4[t] = u4;
    __syncthreads();
    {
        float4 a0 = red4[l], a1 = red4[32+l], a2 = red4[64+l], a3 = red4[96+l];
        u4.x = a0.x+a1.x+a2.x+a3.x; u4.y = a0.y+a1.y+a2.y+a3.y;
        u4.z = a0.z+a1.z+a2.z+a3.z; u4.w = a0.w+a1.w+a2.w+a3.w;
    }

    float* pb_g = g_pbuf + (size_t)s * KC;   // fallback p region, layout [k*cnt+e]

    #pragma unroll
    for (int it = 0; it < 3; it++) {
        // ---- Pass A: p[e][k] = <u_k, x_ek>, track per-capsule max ----
        float m_loc = -1e30f;
        for (int e = w; e < cnt; e += 4) {
            float4 xv = cached ? x4_sh[e*32 + l]
                               : ((const float4*)(g_xn + (size_t)colg[s+e]*DIM))[l];
            float d = u4.x*xv.x + u4.y*xv.y + u4.z*xv.z + u4.w*xv.w;
            d += __shfl_xor_sync(FULLM, d, 1);
            d += __shfl_xor_sync(FULLM, d, 2);
            if ((l & 3) == 0) {
                if (cached) pbuf[cap*PSTR + e] = d;
                else        pb_g[cap*cnt + e] = d;
            }
            m_loc = fmaxf(m_loc, d);
        }
        if ((l & 3) == 0) mred[w*KC + cap] = m_loc;
        __syncthreads();                               // B1

        // ---- softmax + blend + exp (cheap scans over p only) ----
        float m = fmaxf(fmaxf(mred[k16], mred[KC + k16]),
                        fmaxf(mred[2*KC + k16], mred[3*KC + k16]));
        float S = 0.f;
        if (cached) {
            float e1v[(XCAP + 15) / 16];
            #pragma unroll
            for (int q = 0; q < (XCAP + 15) / 16; q++) {
                int e = j16 + q*16;
                float v = 0.f;
                if (e < cnt) v = __expf(pbuf[k16*PSTR + e] - m);
                e1v[q] = v; S += v;
            }
            S += __shfl_xor_sync(FULLM, S, 1);
            S += __shfl_xor_sync(FULLM, S, 2);
            S += __shfl_xor_sync(FULLM, S, 4);
            S += __shfl_xor_sync(FULLM, S, 8);
            float Sinv = 1.f / fmaxf(S, 1e-30f);
            float S2 = 0.f;
            #pragma unroll
            for (int q = 0; q < (XCAP + 15) / 16; q++) {
                int e = j16 + q*16;
                if (e < cnt) {
                    float b = 0.5f * e1v[q] * Sinv + 0.5f * ppr_sh[e];
                    float v2 = __expf(b);
                    pbuf[k16*PSTR + e] = v2;
                    S2 += v2;
                }
            }
            S2 += __shfl_xor_sync(FULLM, S2, 1);
            S2 += __shfl_xor_sync(FULLM, S2, 2);
            S2 += __shfl_xor_sync(FULLM, S2, 4);
            S2 += __shfl_xor_sync(FULLM, S2, 8);
            if (j16 == 0) ssv[k16] = 1.f / fmaxf(S2, 1e-30f);
        } else {
            // fallback: two passes through global p (store e1, reload)
            for (int e = j16; e < cnt; e += 16) {
                float v = __expf(pb_g[k16*cnt + e] - m);
                pb_g[k16*cnt + e] = v; S += v;
            }
            S += __shfl_xor_sync(FULLM, S, 1);
            S += __shfl_xor_sync(FULLM, S, 2);
            S += __shfl_xor_sync(FULLM, S, 4);
            S += __shfl_xor_sync(FULLM, S, 8);
            float Sinv = 1.f / fmaxf(S, 1e-30f);
            float S2 = 0.f;
            for (int e = j16; e < cnt; e += 16) {
                float b = 0.5f * pb_g[k16*cnt + e] * Sinv + 0.5f * pprg[s + e];
                float v2 = __expf(b);
                pb_g[k16*cnt + e] = v2; S2 += v2;
            }
            S2 += __shfl_xor_sync(FULLM, S2, 1);
            S2 += __shfl_xor_sync(FULLM, S2, 2);
            S2 += __shfl_xor_sync(FULLM, S2, 4);
            S2 += __shfl_xor_sync(FULLM, S2, 8);
            if (j16 == 0) ssv[k16] = 1.f / fmaxf(S2, 1e-30f);
        }
        __syncthreads();                               // B2

        // ---- Pass B: u3[d] = (1/S2_cap) * sum_e x_e[d] * w[e][cap] ----
        float4 acc = make_float4(0.f, 0.f, 0.f, 0.f);
        for (int e = w; e < cnt; e += 4) {
            float4 xv = cached ? x4_sh[e*32 + l]
                               : ((const float4*)(g_xn + (size_t)colg[s+e]*DIM))[l];
            float pw = cached ? pbuf[cap*PSTR + e] : pb_g[cap*cnt + e];
            acc.x += xv.x*pw; acc.y += xv.y*pw; acc.z += xv.z*pw; acc.w += xv.w*pw;
        }
        red4[t] = acc;
        __syncthreads();                               // B3
        float s2i = ssv[cap];
        float4 a0 = red4[l], a1 = red4[32+l], a2 = red4[64+l], a3 = red4[96+l];
        float4 un;
        un.x = (a0.x+a1.x+a2.x+a3.x) * s2i;
        un.y = (a0.y+a1.y+a2.y+a3.y) * s2i;
        un.z = (a0.z+a1.z+a2.z+a3.z) * s2i;
        un.w = (a0.w+a1.w+a2.w+a3.w) * s2i;

        if (it < 2) {
            float sq = un.x*un.x + un.y*un.y + un.z*un.z + un.w*un.w;
            sq += __shfl_xor_sync(FULLM, sq, 1);
            sq += __shfl_xor_sync(FULLM, sq, 2);
            float inv = 1.f / fmaxf(sqrtf(sq), 1e-12f);
            u4.x = un.x*inv; u4.y = un.y*inv; u4.z = un.z*inv; u4.w = un.w*inv;
        } else if (w == 0) {
            ((float4*)(out + (size_t)r * DIM))[l] = un;
        }
    }
}

// ---------------------------------------------------------------------------
extern "C" void kernel_launch(void* const* d_in, const int* in_sizes, int n_in,
                              void* d_out, int out_size)
{
    const float* x    = (const float*)d_in[0];   // (N,128) f32
    const float* ppr  = (const float*)d_in[1];   // (E,)    f32
    const int*   row  = (const int*)  d_in[2];   // (E,)    i32 sorted
    const int*   col  = (const int*)  d_in[3];   // (E,)    i32
    float* out = (float*)d_out;

    int n = in_sizes[0] / DIM;
    if (n > NMAX) n = NMAX;
    int E = in_sizes[1];
    if (E > EMAX) E = EMAX;
    if (n <= 0) return;

    const int ncap = n * KC;
    knorm<<<(ncap + 255) / 256, 256>>>(x, ncap);
    krows<<<(n + 1 + 255) / 256, 256>>>(row, n, E);

    // smem: x 32768 + pbuf 8*65*4=2080 + ppr 256 + col 256 + red4 2048
    //       + mred 128 + ssv 32  = 37568 B  -> 6 blocks/SM
    const size_t SMEM = (size_t)XCAP*DIM*4 + (size_t)KC*PSTR*4
                      + XCAP*4 + XCAP*4 + DIM*16 + 32*4 + KC*4;
    cudaFuncSetAttribute(kmain, cudaFuncAttributeMaxDynamicSharedMemorySize,
                         (int)SMEM);
    kmain<<<n, 128, SMEM>>>(ppr, col, out, E);
}

// round 5
// speedup vs baseline: 2.1654x; 1.1841x over previous
#include <cuda_runtime.h>
#include <math.h>

#define DIM   128
#define KC    8
#define NMAX  50000
#define EMAX  1600000
#define XCAP  48            // max edges cached in SMEM per row
#define PSTR  (XCAP + 1)    // pbuf row stride
#define NQ    ((XCAP + 15) / 16)
#define FULLM 0xFFFFFFFFu

__device__ __align__(256) float g_xn[(size_t)NMAX * DIM];   // normalized x (25.6 MB)
__device__ __align__(256) float g_pbuf[(size_t)EMAX * KC];  // fallback p scratch
__device__ int g_rs[NMAX + 1];                              // row CSR offsets

// ---------------------------------------------------------------------------
__global__ void knorm(const float* __restrict__ x, int ncap) {
    int i = blockIdx.x * blockDim.x + threadIdx.x;
    if (i >= ncap) return;
    const float4* src = ((const float4*)x) + (size_t)i * 4;
    float4 a = src[0], b = src[1], c = src[2], d = src[3];
    float s = a.x*a.x + a.y*a.y + a.z*a.z + a.w*a.w
            + b.x*b.x + b.y*b.y + b.z*b.z + b.w*b.w
            + c.x*c.x + c.y*c.y + c.z*c.z + c.w*c.w
            + d.x*d.x + d.y*d.y + d.z*d.z + d.w*d.w;
    float inv = 1.0f / fmaxf(sqrtf(s), 1e-12f);
    a.x*=inv; a.y*=inv; a.z*=inv; a.w*=inv;
    b.x*=inv; b.y*=inv; b.z*=inv; b.w*=inv;
    c.x*=inv; c.y*=inv; c.z*=inv; c.w*=inv;
    d.x*=inv; d.y*=inv; d.z*=inv; d.w*=inv;
    float4* dst = ((float4*)g_xn) + (size_t)i * 4;
    dst[0]=a; dst[1]=b; dst[2]=c; dst[3]=d;
}

// ---------------------------------------------------------------------------
__global__ void krows(const int* __restrict__ row_idx, int n, int E) {
    int r = blockIdx.x * blockDim.x + threadIdx.x;
    if (r > n) return;
    if (r == n) { g_rs[n] = E; return; }
    int lo = 0, hi = E;
    while (lo < hi) {
        int mid = (lo + hi) >> 1;
        if (row_idx[mid] < r) lo = mid + 1; else hi = mid;
    }
    g_rs[r] = lo;
}

// ---------------------------------------------------------------------------
// One 128-thread block per row. Lane l owns dims [4l,4l+4) (float4); each
// warp holds the full u. Warp w handles edges e = w, w+4, ...  Edge count is
// padded to a multiple of 4 (zero x / zero ppr) so all edge loops have
// uniform trip count and unroll into independent chains.
// Softmax mapping: thread t -> capsule t>>4, strip t&15 (in-warp butterflies).
// ---------------------------------------------------------------------------
__global__ void __launch_bounds__(128) kmain(
    const float* __restrict__ pprg,
    const int* __restrict__ colg,
    float* __restrict__ out, int E)
{
    extern __shared__ float smem[];
    float4* x4_sh  = (float4*)smem;                  // XCAP*32 float4 (24 KB)
    float*  pbuf   = smem + XCAP*DIM;                // KC*PSTR
    float*  ppr_sh = pbuf + KC*PSTR;                 // XCAP
    int*    col_sh = (int*)(ppr_sh + XCAP);          // XCAP
    float4* red4   = (float4*)(col_sh + XCAP);       // 128 float4 (2 KB)
    float*  ssv    = (float*)(red4 + DIM);           // 8

    const int r = blockIdx.x;
    const int t = threadIdx.x;
    const int w = t >> 5, l = t & 31;
    const int cap = l >> 2;                // capsule owned by this lane's dims
    const int k16 = t >> 4, j16 = t & 15;  // softmax mapping

    const int s = g_rs[r];
    int cnt = g_rs[r + 1] - s;
    cnt = max(0, min(cnt, E));
    const bool cached = (cnt <= XCAP);
    const int cnt4 = (cnt + 3) & ~3;       // <= XCAP when cached
    const int T4 = cnt4 >> 2;

    float* pb_g = g_pbuf + (size_t)s * KC; // fallback p region [k*cnt + e]

    // ---- stage col/ppr (zero-padded), x tile fused with u-init ----
    float4 u4 = make_float4(0.f, 0.f, 0.f, 0.f);
    if (cached) {
        for (int i = t; i < cnt4; i += 128) {
            col_sh[i] = (i < cnt) ? colg[s + i] : 0;
            ppr_sh[i] = (i < cnt) ? pprg[s + i] : 0.f;
        }
        __syncthreads();
        #pragma unroll 2
        for (int i = 0; i < T4; i++) {
            int e = w + (i << 2);
            float4 xv = make_float4(0.f, 0.f, 0.f, 0.f);
            if (e < cnt) xv = ((const float4*)(g_xn + (size_t)col_sh[e]*DIM))[l];
            x4_sh[e*32 + l] = xv;
            float pe = ppr_sh[e];
            u4.x += xv.x*pe; u4.y += xv.y*pe; u4.z += xv.z*pe; u4.w += xv.w*pe;
        }
    } else {
        for (int e = w; e < cnt; e += 4) {
            float4 xv = ((const float4*)(g_xn + (size_t)colg[s+e]*DIM))[l];
            float pe = pprg[s + e];
            u4.x += xv.x*pe; u4.y += xv.y*pe; u4.z += xv.z*pe; u4.w += xv.w*pe;
        }
    }
    // cross-warp reduce u (all warps end with identical full u)
    red4[t] = u4;
    __syncthreads();
    {
        float4 a0 = red4[l], a1 = red4[32+l], a2 = red4[64+l], a3 = red4[96+l];
        u4.x = a0.x+a1.x+a2.x+a3.x; u4.y = a0.y+a1.y+a2.y+a3.y;
        u4.z = a0.z+a1.z+a2.z+a3.z; u4.w = a0.w+a1.w+a2.w+a3.w;
    }

    #pragma unroll
    for (int it = 0; it < 3; it++) {
        // ---- Pass A: p[e][k] = <u_k, x_ek>  (no loop-carried dependence) ----
        if (cached) {
            #pragma unroll 4
            for (int i = 0; i < T4; i++) {
                int e = w + (i << 2);
                float4 xv = x4_sh[e*32 + l];
                float d = u4.x*xv.x + u4.y*xv.y + u4.z*xv.z + u4.w*xv.w;
                d += __shfl_xor_sync(FULLM, d, 1);
                d += __shfl_xor_sync(FULLM, d, 2);
                if ((l & 3) == 0) pbuf[cap*PSTR + e] = d;
            }
        } else {
            for (int e = w; e < cnt; e += 4) {
                float4 xv = ((const float4*)(g_xn + (size_t)colg[s+e]*DIM))[l];
                float d = u4.x*xv.x + u4.y*xv.y + u4.z*xv.z + u4.w*xv.w;
                d += __shfl_xor_sync(FULLM, d, 1);
                d += __shfl_xor_sync(FULLM, d, 2);
                if ((l & 3) == 0) pb_g[cap*cnt + e] = d;
            }
        }
        __syncthreads();                               // B1

        // ---- softmax + blend + second exp ----
        if (cached) {
            float pv[NQ];
            float m = -1e30f;
            #pragma unroll
            for (int q = 0; q < NQ; q++) {
                int e = j16 + q*16;
                pv[q] = (e < cnt) ? pbuf[k16*PSTR + e] : -1e30f;
                m = fmaxf(m, pv[q]);
            }
            m = fmaxf(m, __shfl_xor_sync(FULLM, m, 1));
            m = fmaxf(m, __shfl_xor_sync(FULLM, m, 2));
            m = fmaxf(m, __shfl_xor_sync(FULLM, m, 4));
            m = fmaxf(m, __shfl_xor_sync(FULLM, m, 8));
            float S = 0.f;
            #pragma unroll
            for (int q = 0; q < NQ; q++) {
                int e = j16 + q*16;
                float v = 0.f;
                if (e < cnt) v = __expf(pv[q] - m);
                pv[q] = v; S += v;
            }
            S += __shfl_xor_sync(FULLM, S, 1);
            S += __shfl_xor_sync(FULLM, S, 2);
            S += __shfl_xor_sync(FULLM, S, 4);
            S += __shfl_xor_sync(FULLM, S, 8);
            float Sinv = 1.f / fmaxf(S, 1e-30f);
            float S2 = 0.f;
            #pragma unroll
            for (int q = 0; q < NQ; q++) {
                int e = j16 + q*16;
                if (e < cnt) {
                    float b = 0.5f * pv[q] * Sinv + 0.5f * ppr_sh[e];
                    float v2 = __expf(b);
                    pbuf[k16*PSTR + e] = v2;
                    S2 += v2;
                }
            }
            S2 += __shfl_xor_sync(FULLM, S2, 1);
            S2 += __shfl_xor_sync(FULLM, S2, 2);
            S2 += __shfl_xor_sync(FULLM, S2, 4);
            S2 += __shfl_xor_sync(FULLM, S2, 8);
            if (j16 == 0) ssv[k16] = 1.f / fmaxf(S2, 1e-30f);
        } else {
            float m = -1e30f;
            for (int e = j16; e < cnt; e += 16)
                m = fmaxf(m, pb_g[k16*cnt + e]);
            m = fmaxf(m, __shfl_xor_sync(FULLM, m, 1));
            m = fmaxf(m, __shfl_xor_sync(FULLM, m, 2));
            m = fmaxf(m, __shfl_xor_sync(FULLM, m, 4));
            m = fmaxf(m, __shfl_xor_sync(FULLM, m, 8));
            float S = 0.f;
            for (int e = j16; e < cnt; e += 16) {
                float v = __expf(pb_g[k16*cnt + e] - m);
                pb_g[k16*cnt + e] = v; S += v;
            }
            S += __shfl_xor_sync(FULLM, S, 1);
            S += __shfl_xor_sync(FULLM, S, 2);
            S += __shfl_xor_sync(FULLM, S, 4);
            S += __shfl_xor_sync(FULLM, S, 8);
            float Sinv = 1.f / fmaxf(S, 1e-30f);
            float S2 = 0.f;
            for (int e = j16; e < cnt; e += 16) {
                float b = 0.5f * pb_g[k16*cnt + e] * Sinv + 0.5f * pprg[s + e];
                float v2 = __expf(b);
                pb_g[k16*cnt + e] = v2; S2 += v2;
            }
            S2 += __shfl_xor_sync(FULLM, S2, 1);
            S2 += __shfl_xor_sync(FULLM, S2, 2);
            S2 += __shfl_xor_sync(FULLM, S2, 4);
            S2 += __shfl_xor_sync(FULLM, S2, 8);
            if (j16 == 0) ssv[k16] = 1.f / fmaxf(S2, 1e-30f);
        }
        __syncthreads();                               // B2

        // ---- Pass B: u3[d] = (1/S2_cap) * sum_e x_e[d] * p2[e][cap] ----
        float4 acc = make_float4(0.f, 0.f, 0.f, 0.f);
        if (cached) {
            #pragma unroll 4
            for (int i = 0; i < T4; i++) {
                int e = w + (i << 2);
                float4 xv = x4_sh[e*32 + l];
                float pw = pbuf[cap*PSTR + e];
                acc.x += xv.x*pw; acc.y += xv.y*pw;
                acc.z += xv.z*pw; acc.w += xv.w*pw;
            }
        } else {
            for (int e = w; e < cnt; e += 4) {
                float4 xv = ((const float4*)(g_xn + (size_t)colg[s+e]*DIM))[l];
                float pw = pb_g[cap*cnt + e];
                acc.x += xv.x*pw; acc.y += xv.y*pw;
                acc.z += xv.z*pw; acc.w += xv.w*pw;
            }
        }
        red4[t] = acc;
        __syncthreads();                               // B3
        float s2i = ssv[cap];
        float4 a0 = red4[l], a1 = red4[32+l], a2 = red4[64+l], a3 = red4[96+l];
        float4 un;
        un.x = (a0.x+a1.x+a2.x+a3.x) * s2i;
        un.y = (a0.y+a1.y+a2.y+a3.y) * s2i;
        un.z = (a0.z+a1.z+a2.z+a3.z) * s2i;
        un.w = (a0.w+a1.w+a2.w+a3.w) * s2i;

        if (it < 2) {
            float sq = un.x*un.x + un.y*un.y + un.z*un.z + un.w*un.w;
            sq += __shfl_xor_sync(FULLM, sq, 1);
            sq += __shfl_xor_sync(FULLM, sq, 2);
            float inv = 1.f / fmaxf(sqrtf(sq), 1e-12f);
            u4.x = un.x*inv; u4.y = un.y*inv; u4.z = un.z*inv; u4.w = un.w*inv;
        } else if (w == 0) {
            ((float4*)(out + (size_t)r * DIM))[l] = un;
        }
    }
}

// ---------------------------------------------------------------------------
extern "C" void kernel_launch(void* const* d_in, const int* in_sizes, int n_in,
                              void* d_out, int out_size)
{
    const float* x    = (const float*)d_in[0];
    const float* ppr  = (const float*)d_in[1];
    const int*   row  = (const int*)  d_in[2];
    const int*   col  = (const int*)  d_in[3];
    float* out = (float*)d_out;

    int n = in_sizes[0] / DIM;
    if (n > NMAX) n = NMAX;
    int E = in_sizes[1];
    if (E > EMAX) E = EMAX;
    if (n <= 0) return;

    const int ncap = n * KC;
    knorm<<<(ncap + 255) / 256, 256>>>(x, ncap);
    krows<<<(n + 1 + 255) / 256, 256>>>(row, n, E);

    // smem: x 24576 + pbuf 1568 + ppr 192 + col 192 + red4 2048 + ssv 32
    //     = 28608 B  -> 7-8 blocks/SM
    const size_t SMEM = (size_t)XCAP*DIM*4 + (size_t)KC*PSTR*4
                      + XCAP*4 + XCAP*4 + DIM*16 + KC*4;
    cudaFuncSetAttribute(kmain, cudaFuncAttributeMaxDynamicSharedMemorySize,
                         (int)SMEM);
    kmain<<<n, 128, SMEM>>>(ppr, col, out, E);
}

// round 6
// speedup vs baseline: 2.5365x; 1.1714x over previous
#include <cuda_runtime.h>
#include <math.h>

#define DIM   128
#define KC    8
#define NMAX  50000
#define EMAX  1600000
#define XCAP  48            // max edges cached in SMEM per row
#define XS    (XCAP + 1)    // x4t edge stride (odd -> conflict-free walks)
#define PSTR  52            // pbuf row stride (52%32=20 -> pass-A stores conflict-free)
#define NQ    ((XCAP + 15) / 16)
#define FULLM 0xFFFFFFFFu

__device__ __align__(256) float g_xn[(size_t)NMAX * DIM];   // normalized x (25.6 MB)
__device__ __align__(256) float g_pbuf[(size_t)EMAX * KC];  // fallback p scratch
__device__ int g_rs[NMAX + 1];                              // row CSR offsets

// ---------------------------------------------------------------------------
__global__ void knorm(const float* __restrict__ x, int ncap) {
    int i = blockIdx.x * blockDim.x + threadIdx.x;
    if (i >= ncap) return;
    const float4* src = ((const float4*)x) + (size_t)i * 4;
    float4 a = src[0], b = src[1], c = src[2], d = src[3];
    float s = a.x*a.x + a.y*a.y + a.z*a.z + a.w*a.w
            + b.x*b.x + b.y*b.y + b.z*b.z + b.w*b.w
            + c.x*c.x + c.y*c.y + c.z*c.z + c.w*c.w
            + d.x*d.x + d.y*d.y + d.z*d.z + d.w*d.w;
    float inv = 1.0f / fmaxf(sqrtf(s), 1e-12f);
    a.x*=inv; a.y*=inv; a.z*=inv; a.w*=inv;
    b.x*=inv; b.y*=inv; b.z*=inv; b.w*=inv;
    c.x*=inv; c.y*=inv; c.z*=inv; c.w*=inv;
    d.x*=inv; d.y*=inv; d.z*=inv; d.w*=inv;
    float4* dst = ((float4*)g_xn) + (size_t)i * 4;
    dst[0]=a; dst[1]=b; dst[2]=c; dst[3]=d;
}

// ---------------------------------------------------------------------------
__global__ void krows(const int* __restrict__ row_idx, int n, int E) {
    int r = blockIdx.x * blockDim.x + threadIdx.x;
    if (r > n) return;
    if (r == n) { g_rs[n] = E; return; }
    int lo = 0, hi = E;
    while (lo < hi) {
        int mid = (lo + hi) >> 1;
        if (row_idx[mid] < r) lo = mid + 1; else hi = mid;
    }
    g_rs[r] = lo;
}

__device__ __forceinline__ float dot4(float4 a, float4 b) {
    return a.x*b.x + a.y*b.y + a.z*b.z + a.w*b.w;
}

// ---------------------------------------------------------------------------
// One 128-thread block per row, 3 iterations fused.
// Cached path layouts:
//   x4t[d4*XS + e]  : transposed x tile, d4 = float4-dim 0..31, e = edge
//   Pass A: lane computes full capsule dot (no shuffles); capsule c8=l&7,
//           edge 4j+(l>>3); q-rotation makes every LDS.128 bank-bijective.
//   Pass B / staging: lane l owns dim-chunk d4=l; warp w edges e=w+4i.
//   Softmax: thread t -> capsule t>>4, strip t&15; NO max subtraction
//            (|p| <= sum ppr <= XCAP -> exp can't overflow).
// ---------------------------------------------------------------------------
__global__ void __launch_bounds__(128) kmain(
    const float* __restrict__ pprg,
    const int* __restrict__ colg,
    float* __restrict__ out, int E)
{
    extern __shared__ float smem[];
    float4* x4t    = (float4*)smem;                   // 32*XS float4 (25088 B)
    float4* red4   = (float4*)(smem + 32*XS*4);       // 128 float4  (2048 B)
    float4* u_sh4  = red4 + DIM;                      // 32 float4   (512 B)
    float*  pbuf   = (float*)(u_sh4 + 32);            // KC*PSTR     (1664 B)
    float*  ppr_sh = pbuf + KC*PSTR;                  // XCAP        (192 B)
    float*  ssv    = ppr_sh + XCAP;                   // 8           (32 B)

    const int r = blockIdx.x;
    const int t = threadIdx.x;
    const int w = t >> 5, l = t & 31;
    const int k16 = t >> 4, j16 = t & 15;   // softmax mapping

    const int s = g_rs[r];
    int cnt = g_rs[r + 1] - s;
    cnt = max(0, min(cnt, E));
    const int cnt4 = (cnt + 3) & ~3;
    const int T4 = cnt4 >> 2;

    if (cnt <= XCAP) {
        // =================== CACHED PATH ===================
        const int c8  = l & 7;        // pass-A capsule
        const int e4  = l >> 3;       // pass-A edge offset in chunk
        const int rot = c8 >> 1;      // q rotation
        const int q0 = (0+rot)&3, q1 = (1+rot)&3, q2 = (2+rot)&3, q3 = (3+rot)&3;
        const int b0 = (4*c8 + q0)*XS, b1 = (4*c8 + q1)*XS,
                  b2 = (4*c8 + q2)*XS, b3 = (4*c8 + q3)*XS;

        // ---- stage col/ppr, x tile (transposed) fused with u-init ----
        int* col_sh = (int*)pbuf;     // union: col only needed during staging
        for (int i = t; i < cnt4; i += 128) {
            col_sh[i] = (i < cnt) ? colg[s + i] : 0;
            ppr_sh[i] = (i < cnt) ? pprg[s + i] : 0.f;
        }
        __syncthreads();
        float4 ua = make_float4(0.f,0.f,0.f,0.f);
        #pragma unroll 4
        for (int i = 0; i < T4; i++) {
            int e = w + (i << 2);
            float4 xv = make_float4(0.f,0.f,0.f,0.f);
            if (e < cnt) xv = ((const float4*)(g_xn + (size_t)col_sh[e]*DIM))[l];
            x4t[l*XS + e] = xv;
            float pe = ppr_sh[e];
            ua.x += xv.x*pe; ua.y += xv.y*pe; ua.z += xv.z*pe; ua.w += xv.w*pe;
        }
        red4[t] = ua;
        __syncthreads();
        {   // u init (unnormalized), broadcast to u_sh (every warp, same values)
            float4 a0 = red4[l], a1 = red4[32+l], a2 = red4[64+l], a3 = red4[96+l];
            float4 un;
            un.x = a0.x+a1.x+a2.x+a3.x; un.y = a0.y+a1.y+a2.y+a3.y;
            un.z = a0.z+a1.z+a2.z+a3.z; un.w = a0.w+a1.w+a2.w+a3.w;
            u_sh4[l] = un;
        }

        #pragma unroll
        for (int it = 0; it < 3; it++) {
            // ---- Pass A: full-capsule dot per lane, zero shuffles ----
            float4 uq0 = u_sh4[c8*4 + q0];
            float4 uq1 = u_sh4[c8*4 + q1];
            float4 uq2 = u_sh4[c8*4 + q2];
            float4 uq3 = u_sh4[c8*4 + q3];
            #pragma unroll 3
            for (int j = w; j < T4; j += 4) {
                int e = (j << 2) + e4;
                float d = dot4(uq0, x4t[b0 + e]) + dot4(uq1, x4t[b1 + e])
                        + dot4(uq2, x4t[b2 + e]) + dot4(uq3, x4t[b3 + e]);
                pbuf[c8*PSTR + e] = d;
            }
            __syncthreads();                           // B1

            // ---- softmax (no max) + blend + second exp ----
            float pv[NQ];
            float S = 0.f;
            #pragma unroll
            for (int q = 0; q < NQ; q++) {
                int e = j16 + q*16;
                float v = 0.f;
                if (e < cnt) v = __expf(pbuf[k16*PSTR + e]);
                pv[q] = v; S += v;
            }
            S += __shfl_xor_sync(FULLM, S, 1);
            S += __shfl_xor_sync(FULLM, S, 2);
            S += __shfl_xor_sync(FULLM, S, 4);
            S += __shfl_xor_sync(FULLM, S, 8);
            float Sinv = 1.f / fmaxf(S, 1e-30f);
            float S2 = 0.f;
            #pragma unroll
            for (int q = 0; q < NQ; q++) {
                int e = j16 + q*16;
                if (e < cnt) {
                    float b = 0.5f * pv[q] * Sinv + 0.5f * ppr_sh[e];
                    float v2 = __expf(b);
                    pbuf[k16*PSTR + e] = v2;
                    S2 += v2;
                }
            }
            S2 += __shfl_xor_sync(FULLM, S2, 1);
            S2 += __shfl_xor_sync(FULLM, S2, 2);
            S2 += __shfl_xor_sync(FULLM, S2, 4);
            S2 += __shfl_xor_sync(FULLM, S2, 8);
            if (j16 == 0) ssv[k16] = 1.f / fmaxf(S2, 1e-30f);
            __syncthreads();                           // B2

            // ---- Pass B: dims layout, pad edges contribute 0 (x=0) ----
            float4 acc = make_float4(0.f,0.f,0.f,0.f);
            const int pb = (l >> 2) * PSTR;
            #pragma unroll 4
            for (int i = 0; i < T4; i++) {
                int e = w + (i << 2);
                float4 xv = x4t[l*XS + e];
                float pw = pbuf[pb + e];
                acc.x += xv.x*pw; acc.y += xv.y*pw;
                acc.z += xv.z*pw; acc.w += xv.w*pw;
            }
            red4[t] = acc;
            __syncthreads();                           // B3

            float s2i = ssv[l >> 2];
            float4 a0 = red4[l], a1 = red4[32+l], a2 = red4[64+l], a3 = red4[96+l];
            float4 un;
            un.x = (a0.x+a1.x+a2.x+a3.x) * s2i;
            un.y = (a0.y+a1.y+a2.y+a3.y) * s2i;
            un.z = (a0.z+a1.z+a2.z+a3.z) * s2i;
            un.w = (a0.w+a1.w+a2.w+a3.w) * s2i;

            if (it < 2) {
                float sq = un.x*un.x + un.y*un.y + un.z*un.z + un.w*un.w;
                sq += __shfl_xor_sync(FULLM, sq, 1);
                sq += __shfl_xor_sync(FULLM, sq, 2);
                float inv = 1.f / fmaxf(sqrtf(sq), 1e-12f);
                un.x *= inv; un.y *= inv; un.z *= inv; un.w *= inv;
                u_sh4[l] = un;   // every warp writes identical values
            } else if (w == 0) {
                ((float4*)(out + (size_t)r * DIM))[l] = un;
            }
        }
    } else {
        // =================== FALLBACK PATH (rare) ===================
        const int cap = l >> 2;
        float* pb_g = g_pbuf + (size_t)s * KC;   // [k*cnt + e]

        float4 u4 = make_float4(0.f,0.f,0.f,0.f);
        for (int e = w; e < cnt; e += 4) {
            float4 xv = ((const float4*)(g_xn + (size_t)colg[s+e]*DIM))[l];
            float pe = pprg[s + e];
            u4.x += xv.x*pe; u4.y += xv.y*pe; u4.z += xv.z*pe; u4.w += xv.w*pe;
        }
        red4[t] = u4;
        __syncthreads();
        {
            float4 a0 = red4[l], a1 = red4[32+l], a2 = red4[64+l], a3 = red4[96+l];
            u4.x = a0.x+a1.x+a2.x+a3.x; u4.y = a0.y+a1.y+a2.y+a3.y;
            u4.z = a0.z+a1.z+a2.z+a3.z; u4.w = a0.w+a1.w+a2.w+a3.w;
        }

        #pragma unroll
        for (int it = 0; it < 3; it++) {
            for (int e = w; e < cnt; e += 4) {
                float4 xv = ((const float4*)(g_xn + (size_t)colg[s+e]*DIM))[l];
                float d = u4.x*xv.x + u4.y*xv.y + u4.z*xv.z + u4.w*xv.w;
                d += __shfl_xor_sync(FULLM, d, 1);
                d += __shfl_xor_sync(FULLM, d, 2);
                if ((l & 3) == 0) pb_g[cap*cnt + e] = d;
            }
            __syncthreads();

            float m = -1e30f;
            for (int e = j16; e < cnt; e += 16)
                m = fmaxf(m, pb_g[k16*cnt + e]);
            m = fmaxf(m, __shfl_xor_sync(FULLM, m, 1));
            m = fmaxf(m, __shfl_xor_sync(FULLM, m, 2));
            m = fmaxf(m, __shfl_xor_sync(FULLM, m, 4));
            m = fmaxf(m, __shfl_xor_sync(FULLM, m, 8));
            float S = 0.f;
            for (int e = j16; e < cnt; e += 16) {
                float v = __expf(pb_g[k16*cnt + e] - m);
                pb_g[k16*cnt + e] = v; S += v;
            }
            S += __shfl_xor_sync(FULLM, S, 1);
            S += __shfl_xor_sync(FULLM, S, 2);
            S += __shfl_xor_sync(FULLM, S, 4);
            S += __shfl_xor_sync(FULLM, S, 8);
            float Sinv = 1.f / fmaxf(S, 1e-30f);
            float S2 = 0.f;
            for (int e = j16; e < cnt; e += 16) {
                float b = 0.5f * pb_g[k16*cnt + e] * Sinv + 0.5f * pprg[s + e];
                float v2 = __expf(b);
                pb_g[k16*cnt + e] = v2; S2 += v2;
            }
            S2 += __shfl_xor_sync(FULLM, S2, 1);
            S2 += __shfl_xor_sync(FULLM, S2, 2);
            S2 += __shfl_xor_sync(FULLM, S2, 4);
            S2 += __shfl_xor_sync(FULLM, S2, 8);
            if (j16 == 0) ssv[k16] = 1.f / fmaxf(S2, 1e-30f);
            __syncthreads();

            float4 acc = make_float4(0.f,0.f,0.f,0.f);
            for (int e = w; e < cnt; e += 4) {
                float4 xv = ((const float4*)(g_xn + (size_t)colg[s+e]*DIM))[l];
                float pw = pb_g[cap*cnt + e];
                acc.x += xv.x*pw; acc.y += xv.y*pw;
                acc.z += xv.z*pw; acc.w += xv.w*pw;
            }
            red4[t] = acc;
            __syncthreads();
            float s2i = ssv[cap];
            float4 a0 = red4[l], a1 = red4[32+l], a2 = red4[64+l], a3 = red4[96+l];
            float4 un;
            un.x = (a0.x+a1.x+a2.x+a3.x) * s2i;
            un.y = (a0.y+a1.y+a2.y+a3.y) * s2i;
            un.z = (a0.z+a1.z+a2.z+a3.z) * s2i;
            un.w = (a0.w+a1.w+a2.w+a3.w) * s2i;

            if (it < 2) {
                float sq = un.x*un.x + un.y*un.y + un.z*un.z + un.w*un.w;
                sq += __shfl_xor_sync(FULLM, sq, 1);
                sq += __shfl_xor_sync(FULLM, sq, 2);
                float inv = 1.f / fmaxf(sqrtf(sq), 1e-12f);
                u4.x = un.x*inv; u4.y = un.y*inv; u4.z = un.z*inv; u4.w = un.w*inv;
            } else if (w == 0) {
                ((float4*)(out + (size_t)r * DIM))[l] = un;
            }
        }
    }
}

// ---------------------------------------------------------------------------
extern "C" void kernel_launch(void* const* d_in, const int* in_sizes, int n_in,
                              void* d_out, int out_size)
{
    const float* x    = (const float*)d_in[0];
    const float* ppr  = (const float*)d_in[1];
    const int*   row  = (const int*)  d_in[2];
    const int*   col  = (const int*)  d_in[3];
    float* out = (float*)d_out;

    int n = in_sizes[0] / DIM;
    if (n > NMAX) n = NMAX;
    int E = in_sizes[1];
    if (E > EMAX) E = EMAX;
    if (n <= 0) return;

    const int ncap = n * KC;
    knorm<<<(ncap + 255) / 256, 256>>>(x, ncap);
    krows<<<(n + 1 + 255) / 256, 256>>>(row, n, E);

    // smem floats: x4t 32*XS*4 + red4 512 + u_sh 128 + pbuf 8*PSTR + ppr 48 + ssv 8
    const size_t SMEM = (size_t)(32*XS*4 + DIM*4 + 32*4 + KC*PSTR + XCAP + KC)
                        * sizeof(float);   // 29536 B -> 7 blocks/SM
    cudaFuncSetAttribute(kmain, cudaFuncAttributeMaxDynamicSharedMemorySize,
                         (int)SMEM);
    kmain<<<n, 128, SMEM>>>(ppr, col, out, E);
}

// round 8
// speedup vs baseline: 2.6070x; 1.0278x over previous
#include <cuda_runtime.h>
#include <math.h>

#define DIM   128
#define KC    8
#define NMAX  50000
#define EMAX  1600000
#define XCAP  44            // max edges cached in SMEM per row (multiple of 4)
#define XS    (XCAP + 1)    // x4t edge stride (odd -> conflict-free walks)
#define PSTR  52            // pbuf row stride (20c8 mod 32 bijective -> pass-A stores conflict-free)
#define NQ    ((XCAP + 15) / 16)
#define FULLM 0xFFFFFFFFu

__device__ __align__(256) float g_xn[(size_t)NMAX * DIM];   // normalized x (25.6 MB)
__device__ __align__(256) float g_pbuf[(size_t)EMAX * KC];  // fallback p scratch
__device__ int g_rs[NMAX + 1];                              // row CSR offsets

// ---------------------------------------------------------------------------
__global__ void knorm(const float* __restrict__ x, int ncap) {
    int i = blockIdx.x * blockDim.x + threadIdx.x;
    if (i >= ncap) return;
    const float4* src = ((const float4*)x) + (size_t)i * 4;
    float4 a = src[0], b = src[1], c = src[2], d = src[3];
    float s = a.x*a.x + a.y*a.y + a.z*a.z + a.w*a.w
            + b.x*b.x + b.y*b.y + b.z*b.z + b.w*b.w
            + c.x*c.x + c.y*c.y + c.z*c.z + c.w*c.w
            + d.x*d.x + d.y*d.y + d.z*d.z + d.w*d.w;
    float inv = 1.0f / fmaxf(sqrtf(s), 1e-12f);
    a.x*=inv; a.y*=inv; a.z*=inv; a.w*=inv;
    b.x*=inv; b.y*=inv; b.z*=inv; b.w*=inv;
    c.x*=inv; c.y*=inv; c.z*=inv; c.w*=inv;
    d.x*=inv; d.y*=inv; d.z*=inv; d.w*=inv;
    float4* dst = ((float4*)g_xn) + (size_t)i * 4;
    dst[0]=a; dst[1]=b; dst[2]=c; dst[3]=d;
}

// ---------------------------------------------------------------------------
__global__ void krows(const int* __restrict__ row_idx, int n, int E) {
    int r = blockIdx.x * blockDim.x + threadIdx.x;
    if (r > n) return;
    if (r == n) { g_rs[n] = E; return; }
    int lo = 0, hi = E;
    while (lo < hi) {
        int mid = (lo + hi) >> 1;
        if (row_idx[mid] < r) lo = mid + 1; else hi = mid;
    }
    g_rs[r] = lo;
}

__device__ __forceinline__ float dot4(float4 a, float4 b) {
    return a.x*b.x + a.y*b.y + a.z*b.z + a.w*b.w;
}

// ---------------------------------------------------------------------------
// One 128-thread block per row, 3 iterations fused. 8 blocks/SM.
// Cached path layouts:
//   x4t[d4*XS + e]  : transposed x tile, d4 = float4-dim 0..31, e = edge
//   Pass A: lane computes full capsule dot (no shuffles); capsule c8=l&7,
//           edge 4j+(l>>3); q-rotation spreads the LDS.128 bank pattern.
//   Pass B / staging: lane l owns dim-chunk d4=l; warp w edges e=w+4i.
//   Softmax: thread t -> capsule t>>4, strip t&15; NO max subtraction
//            (|p| <= sum ppr <= XCAP -> exp can't overflow fp32).
// ---------------------------------------------------------------------------
__global__ void __launch_bounds__(128, 8) kmain(
    const float* __restrict__ pprg,
    const int* __restrict__ colg,
    float* __restrict__ out, int E)
{
    extern __shared__ float smem[];
    float4* x4t    = (float4*)smem;                   // 32*XS float4 (23040 B)
    float4* red4   = (float4*)(smem + 32*XS*4);       // 128 float4  (2048 B)
    float4* u_sh4  = red4 + DIM;                      // 32 float4   (512 B)
    float*  pbuf   = (float*)(u_sh4 + 32);            // KC*PSTR     (1664 B)
    float*  ppr_sh = pbuf + KC*PSTR;                  // XCAP        (176 B)
    float*  ssv    = ppr_sh + XCAP;                   // 8           (32 B)

    const int r = blockIdx.x;
    const int t = threadIdx.x;
    const int w = t >> 5, l = t & 31;
    const int k16 = t >> 4, j16 = t & 15;   // softmax mapping

    const int s = g_rs[r];
    int cnt = g_rs[r + 1] - s;
    cnt = max(0, min(cnt, E));
    const int cnt4 = (cnt + 3) & ~3;
    const int T4 = cnt4 >> 2;

    if (cnt <= XCAP) {
        // =================== CACHED PATH ===================
        const int c8  = l & 7;        // pass-A capsule
        const int e4  = l >> 3;       // pass-A edge offset in chunk
        const int rot = c8 >> 1;      // q rotation
        const int q0 = (0+rot)&3, q1 = (1+rot)&3, q2 = (2+rot)&3, q3 = (3+rot)&3;
        const int b0 = (4*c8 + q0)*XS, b1 = (4*c8 + q1)*XS,
                  b2 = (4*c8 + q2)*XS, b3 = (4*c8 + q3)*XS;

        // ---- stage col/ppr, x tile (transposed) fused with u-init ----
        int* col_sh = (int*)pbuf;     // union: col only needed during staging
        for (int i = t; i < cnt4; i += 128) {
            col_sh[i] = (i < cnt) ? colg[s + i] : 0;
            ppr_sh[i] = (i < cnt) ? pprg[s + i] : 0.f;
        }
        __syncthreads();
        float4 ua = make_float4(0.f,0.f,0.f,0.f);
        #pragma unroll 4
        for (int i = 0; i < T4; i++) {
            int e = w + (i << 2);
            float4 xv = make_float4(0.f,0.f,0.f,0.f);
            if (e < cnt) xv = ((const float4*)(g_xn + (size_t)col_sh[e]*DIM))[l];
            x4t[l*XS + e] = xv;
            float pe = ppr_sh[e];
            ua.x += xv.x*pe; ua.y += xv.y*pe; ua.z += xv.z*pe; ua.w += xv.w*pe;
        }
        red4[t] = ua;
        __syncthreads();
        {   // u init (unnormalized), broadcast to u_sh (every warp, same values)
            float4 a0 = red4[l], a1 = red4[32+l], a2 = red4[64+l], a3 = red4[96+l];
            float4 un;
            un.x = a0.x+a1.x+a2.x+a3.x; un.y = a0.y+a1.y+a2.y+a3.y;
            un.z = a0.z+a1.z+a2.z+a3.z; un.w = a0.w+a1.w+a2.w+a3.w;
            u_sh4[l] = un;
        }

        #pragma unroll
        for (int it = 0; it < 3; it++) {
            // ---- Pass A: full-capsule dot per lane, zero shuffles ----
            float4 uq0 = u_sh4[c8*4 + q0];
            float4 uq1 = u_sh4[c8*4 + q1];
            float4 uq2 = u_sh4[c8*4 + q2];
            float4 uq3 = u_sh4[c8*4 + q3];
            #pragma unroll 3
            for (int j = w; j < T4; j += 4) {
                int e = (j << 2) + e4;
                float d = dot4(uq0, x4t[b0 + e]) + dot4(uq1, x4t[b1 + e])
                        + dot4(uq2, x4t[b2 + e]) + dot4(uq3, x4t[b3 + e]);
                pbuf[c8*PSTR + e] = d;
            }
            __syncthreads();                           // B1

            // ---- softmax (no max) + blend + second exp ----
            float pv[NQ];
            float S = 0.f;
            #pragma unroll
            for (int q = 0; q < NQ; q++) {
                int e = j16 + q*16;
                float v = 0.f;
                if (e < cnt) v = __expf(pbuf[k16*PSTR + e]);
                pv[q] = v; S += v;
            }
            S += __shfl_xor_sync(FULLM, S, 1);
            S += __shfl_xor_sync(FULLM, S, 2);
            S += __shfl_xor_sync(FULLM, S, 4);
            S += __shfl_xor_sync(FULLM, S, 8);
            float Sinv = 1.f / fmaxf(S, 1e-30f);
            float S2 = 0.f;
            #pragma unroll
            for (int q = 0; q < NQ; q++) {
                int e = j16 + q*16;
                if (e < cnt) {
                    float b = 0.5f * pv[q] * Sinv + 0.5f * ppr_sh[e];
                    float v2 = __expf(b);
                    pbuf[k16*PSTR + e] = v2;
                    S2 += v2;
                }
            }
            S2 += __shfl_xor_sync(FULLM, S2, 1);
            S2 += __shfl_xor_sync(FULLM, S2, 2);
            S2 += __shfl_xor_sync(FULLM, S2, 4);
            S2 += __shfl_xor_sync(FULLM, S2, 8);
            if (j16 == 0) ssv[k16] = 1.f / fmaxf(S2, 1e-30f);
            __syncthreads();                           // B2

            // ---- Pass B: dims layout, pad edges contribute 0 (x=0) ----
            float4 acc = make_float4(0.f,0.f,0.f,0.f);
            const int pb = (l >> 2) * PSTR;
            #pragma unroll 4
            for (int i = 0; i < T4; i++) {
                int e = w + (i << 2);
                float4 xv = x4t[l*XS + e];
                float pw = pbuf[pb + e];
                acc.x += xv.x*pw; acc.y += xv.y*pw;
                acc.z += xv.z*pw; acc.w += xv.w*pw;
            }
            red4[t] = acc;
            __syncthreads();                           // B3

            float s2i = ssv[l >> 2];
            float4 a0 = red4[l], a1 = red4[32+l], a2 = red4[64+l], a3 = red4[96+l];
            float4 un;
            un.x = (a0.x+a1.x+a2.x+a3.x) * s2i;
            un.y = (a0.y+a1.y+a2.y+a3.y) * s2i;
            un.z = (a0.z+a1.z+a2.z+a3.z) * s2i;
            un.w = (a0.w+a1.w+a2.w+a3.w) * s2i;

            if (it < 2) {
                float sq = un.x*un.x + un.y*un.y + un.z*un.z + un.w*un.w;
                sq += __shfl_xor_sync(FULLM, sq, 1);
                sq += __shfl_xor_sync(FULLM, sq, 2);
                float inv = 1.f / fmaxf(sqrtf(sq), 1e-12f);
                un.x *= inv; un.y *= inv; un.z *= inv; un.w *= inv;
                u_sh4[l] = un;   // every warp writes identical values
            } else if (w == 0) {
                ((float4*)(out + (size_t)r * DIM))[l] = un;
            }
        }
    } else {
        // =================== FALLBACK PATH (~2% of rows) ===================
        const int cap = l >> 2;
        float* pb_g = g_pbuf + (size_t)s * KC;   // [k*cnt + e]

        float4 u4 = make_float4(0.f,0.f,0.f,0.f);
        for (int e = w; e < cnt; e += 4) {
            float4 xv = ((const float4*)(g_xn + (size_t)colg[s+e]*DIM))[l];
            float pe = pprg[s + e];
            u4.x += xv.x*pe; u4.y += xv.y*pe; u4.z += xv.z*pe; u4.w += xv.w*pe;
        }
        red4[t] = u4;
        __syncthreads();
        {
            float4 a0 = red4[l], a1 = red4[32+l], a2 = red4[64+l], a3 = red4[96+l];
            u4.x = a0.x+a1.x+a2.x+a3.x; u4.y = a0.y+a1.y+a2.y+a3.y;
            u4.z = a0.z+a1.z+a2.z+a3.z; u4.w = a0.w+a1.w+a2.w+a3.w;
        }

        #pragma unroll
        for (int it = 0; it < 3; it++) {
            for (int e = w; e < cnt; e += 4) {
                float4 xv = ((const float4*)(g_xn + (size_t)colg[s+e]*DIM))[l];
                float d = u4.x*xv.x + u4.y*xv.y + u4.z*xv.z + u4.w*xv.w;
                d += __shfl_xor_sync(FULLM, d, 1);
                d += __shfl_xor_sync(FULLM, d, 2);
                if ((l & 3) == 0) pb_g[cap*cnt + e] = d;
            }
            __syncthreads();

            float m = -1e30f;
            for (int e = j16; e < cnt; e += 16)
                m = fmaxf(m, pb_g[k16*cnt + e]);
            m = fmaxf(m, __shfl_xor_sync(FULLM, m, 1));
            m = fmaxf(m, __shfl_xor_sync(FULLM, m, 2));
            m = fmaxf(m, __shfl_xor_sync(FULLM, m, 4));
            m = fmaxf(m, __shfl_xor_sync(FULLM, m, 8));
            float S = 0.f;
            for (int e = j16; e < cnt; e += 16) {
                float v = __expf(pb_g[k16*cnt + e] - m);
                pb_g[k16*cnt + e] = v; S += v;
            }
            S += __shfl_xor_sync(FULLM, S, 1);
            S += __shfl_xor_sync(FULLM, S, 2);
            S += __shfl_xor_sync(FULLM, S, 4);
            S += __shfl_xor_sync(FULLM, S, 8);
            float Sinv = 1.f / fmaxf(S, 1e-30f);
            float S2 = 0.f;
            for (int e = j16; e < cnt; e += 16) {
                float b = 0.5f * pb_g[k16*cnt + e] * Sinv + 0.5f * pprg[s + e];
                float v2 = __expf(b);
                pb_g[k16*cnt + e] = v2; S2 += v2;
            }
            S2 += __shfl_xor_sync(FULLM, S2, 1);
            S2 += __shfl_xor_sync(FULLM, S2, 2);
            S2 += __shfl_xor_sync(FULLM, S2, 4);
            S2 += __shfl_xor_sync(FULLM, S2, 8);
            if (j16 == 0) ssv[k16] = 1.f / fmaxf(S2, 1e-30f);
            __syncthreads();

            float4 acc = make_float4(0.f,0.f,0.f,0.f);
            for (int e = w; e < cnt; e += 4) {
                float4 xv = ((const float4*)(g_xn + (size_t)colg[s+e]*DIM))[l];
                float pw = pb_g[cap*cnt + e];
                acc.x += xv.x*pw; acc.y += xv.y*pw;
                acc.z += xv.z*pw; acc.w += xv.w*pw;
            }
            red4[t] = acc;
            __syncthreads();
            float s2i = ssv[cap];
            float4 a0 = red4[l], a1 = red4[32+l], a2 = red4[64+l], a3 = red4[96+l];
            float4 un;
            un.x = (a0.x+a1.x+a2.x+a3.x) * s2i;
            un.y = (a0.y+a1.y+a2.y+a3.y) * s2i;
            un.z = (a0.z+a1.z+a2.z+a3.z) * s2i;
            un.w = (a0.w+a1.w+a2.w+a3.w) * s2i;

            if (it < 2) {
                float sq = un.x*un.x + un.y*un.y + un.z*un.z + un.w*un.w;
                sq += __shfl_xor_sync(FULLM, sq, 1);
                sq += __shfl_xor_sync(FULLM, sq, 2);
                float inv = 1.f / fmaxf(sqrtf(sq), 1e-12f);
                u4.x = un.x*inv; u4.y = un.y*inv; u4.z = un.z*inv; u4.w = un.w*inv;
            } else if (w == 0) {
                ((float4*)(out + (size_t)r * DIM))[l] = un;
            }
        }
    }
}

// ---------------------------------------------------------------------------
extern "C" void kernel_launch(void* const* d_in, const int* in_sizes, int n_in,
                              void* d_out, int out_size)
{
    const float* x    = (const float*)d_in[0];
    const float* ppr  = (const float*)d_in[1];
    const int*   row  = (const int*)  d_in[2];
    const int*   col  = (const int*)  d_in[3];
    float* out = (float*)d_out;

    int n = in_sizes[0] / DIM;
    if (n > NMAX) n = NMAX;
    int E = in_sizes[1];
    if (E > EMAX) E = EMAX;
    if (n <= 0) return;

    const int ncap = n * KC;
    knorm<<<(ncap + 255) / 256, 256>>>(x, ncap);
    krows<<<(n + 1 + 255) / 256, 256>>>(row, n, E);

    // smem floats: x4t 32*XS*4 + red4 512 + u_sh 128 + pbuf 8*PSTR + ppr 44 + ssv 8
    const size_t SMEM = (size_t)(32*XS*4 + DIM*4 + 32*4 + KC*PSTR + XCAP + KC)
                        * sizeof(float);   // 27472 B -> 8 blocks/SM
    cudaFuncSetAttribute(kmain, cudaFuncAttributeMaxDynamicSharedMemorySize,
                         (int)SMEM);
    kmain<<<n, 128, SMEM>>>(ppr, col, out, E);
}

// round 10
// speedup vs baseline: 2.7127x; 1.0405x over previous
#include <cuda_runtime.h>
#include <math.h>

#define DIM   128
#define KC    8
#define NMAX  50000
#define EMAX  1600000
#define XCAP  44            // max edges in register cache per row (multiple of 4)
#define T4MAX (XCAP / 4)    // 11 float4 per thread
#define PSTR  52            // pbuf row stride (20c mod 32 bijective -> conflict-free)
#define NQ    ((XCAP + 15) / 16)
#define FULLM 0xFFFFFFFFu

__device__ __align__(256) float g_xn[(size_t)NMAX * DIM];   // normalized x (25.6 MB)
__device__ __align__(256) float g_pbuf[(size_t)EMAX * KC];  // fallback p scratch
__device__ int g_rs[NMAX + 1];                              // row CSR offsets

// ---------------------------------------------------------------------------
__global__ void knorm(const float* __restrict__ x, int ncap) {
    int i = blockIdx.x * blockDim.x + threadIdx.x;
    if (i >= ncap) return;
    const float4* src = ((const float4*)x) + (size_t)i * 4;
    float4 a = src[0], b = src[1], c = src[2], d = src[3];
    float s = a.x*a.x + a.y*a.y + a.z*a.z + a.w*a.w
            + b.x*b.x + b.y*b.y + b.z*b.z + b.w*b.w
            + c.x*c.x + c.y*c.y + c.z*c.z + c.w*c.w
            + d.x*d.x + d.y*d.y + d.z*d.z + d.w*d.w;
    float inv = 1.0f / fmaxf(sqrtf(s), 1e-12f);
    a.x*=inv; a.y*=inv; a.z*=inv; a.w*=inv;
    b.x*=inv; b.y*=inv; b.z*=inv; b.w*=inv;
    c.x*=inv; c.y*=inv; c.z*=inv; c.w*=inv;
    d.x*=inv; d.y*=inv; d.z*=inv; d.w*=inv;
    float4* dst = ((float4*)g_xn) + (size_t)i * 4;
    dst[0]=a; dst[1]=b; dst[2]=c; dst[3]=d;
}

// ---------------------------------------------------------------------------
__global__ void krows(const int* __restrict__ row_idx, int n, int E) {
    int r = blockIdx.x * blockDim.x + threadIdx.x;
    if (r > n) return;
    if (r == n) { g_rs[n] = E; return; }
    int lo = 0, hi = E;
    while (lo < hi) {
        int mid = (lo + hi) >> 1;
        if (row_idx[mid] < r) lo = mid + 1; else hi = mid;
    }
    g_rs[r] = lo;
}

__device__ __forceinline__ float dot4(float4 a, float4 b) {
    return a.x*b.x + a.y*b.y + a.z*b.z + a.w*b.w;
}

// ---------------------------------------------------------------------------
// One 128-thread block per row, 3 iterations fused.
// REGISTER-RESIDENT x tile: thread (w,l) holds x[col[e]] float4 #l for its
// edges e = w + 4i (i < 11) in registers across all iterations. No SMEM tile.
//   Pass A: d = dot4(u4, xv[i]); 2-SHFL butterfly over the 4 lanes of
//           capsule cgrp = l>>2; lane leader stores pbuf[cgrp*PSTR + e].
//   Softmax: thread t -> capsule t>>4, strip t&15; no max subtraction
//            (|p| <= sum ppr <= XCAP -> exp can't overflow fp32).
//   Pass B: acc += xv[i] * pbuf[cgrp*PSTR + e]; cross-warp reduce via red4.
// ---------------------------------------------------------------------------
__global__ void __launch_bounds__(128, 6) kmain(
    const float* __restrict__ pprg,
    const int* __restrict__ colg,
    float* __restrict__ out, int E)
{
    extern __shared__ float smem[];
    float*  pbuf   = smem;                            // KC*PSTR (1664 B)
    float*  ppr_sh = pbuf + KC*PSTR;                  // XCAP
    float*  ssv    = ppr_sh + XCAP;                   // 8
    float4* red4   = (float4*)(ssv + KC);             // 128 float4 (2048 B)

    const int r = blockIdx.x;
    const int t = threadIdx.x;
    const int w = t >> 5, l = t & 31;
    const int cgrp = l >> 2;                // capsule of this lane's dims
    const int k16 = t >> 4, j16 = t & 15;   // softmax mapping

    const int s = g_rs[r];
    int cnt = g_rs[r + 1] - s;
    cnt = max(0, min(cnt, E));
    const int cnt4 = (cnt + 3) & ~3;
    const int T4 = cnt4 >> 2;

    if (cnt <= XCAP) {
        // =================== REGISTER-CACHED PATH ===================
        int* col_sh = (int*)pbuf;     // union: col only needed during staging
        for (int i = t; i < cnt4; i += 128) {
            col_sh[i] = (i < cnt) ? colg[s + i] : 0;
            ppr_sh[i] = (i < cnt) ? pprg[s + i] : 0.f;
        }
        __syncthreads();

        // gather x into registers (up to 11 independent loads), fused u-init
        float4 xv[T4MAX];
        float4 u4 = make_float4(0.f,0.f,0.f,0.f);
        #pragma unroll
        for (int i = 0; i < T4MAX; i++) {
            int e = w + (i << 2);
            float4 v = make_float4(0.f,0.f,0.f,0.f);
            float pe = 0.f;
            if (i < T4) {
                if (e < cnt) v = ((const float4*)(g_xn + (size_t)col_sh[e]*DIM))[l];
                pe = ppr_sh[e];
            }
            xv[i] = v;
            u4.x += v.x*pe; u4.y += v.y*pe; u4.z += v.z*pe; u4.w += v.w*pe;
        }
        red4[t] = u4;
        __syncthreads();
        {   // cross-warp reduce: every thread gets full dims 4l..4l+4 of u
            float4 a0 = red4[l], a1 = red4[32+l], a2 = red4[64+l], a3 = red4[96+l];
            u4.x = a0.x+a1.x+a2.x+a3.x; u4.y = a0.y+a1.y+a2.y+a3.y;
            u4.z = a0.z+a1.z+a2.z+a3.z; u4.w = a0.w+a1.w+a2.w+a3.w;
        }

        #pragma unroll
        for (int it = 0; it < 3; it++) {
            __syncthreads();   // pbuf reuse: prior softmax/pass-B reads done

            // ---- Pass A: register dot + 4-lane butterfly ----
            #pragma unroll
            for (int i = 0; i < T4MAX; i++) {
                if (i < T4) {
                    int e = w + (i << 2);
                    float d = dot4(u4, xv[i]);
                    d += __shfl_xor_sync(FULLM, d, 1);
                    d += __shfl_xor_sync(FULLM, d, 2);
                    if ((l & 3) == 0) pbuf[cgrp*PSTR + e] = d;
                }
            }
            __syncthreads();                           // B1

            // ---- softmax (no max) + blend + second exp ----
            float pv[NQ];
            float S = 0.f;
            #pragma unroll
            for (int q = 0; q < NQ; q++) {
                int e = j16 + q*16;
                float v = 0.f;
                if (e < cnt) v = __expf(pbuf[k16*PSTR + e]);
                pv[q] = v; S += v;
            }
            S += __shfl_xor_sync(FULLM, S, 1);
            S += __shfl_xor_sync(FULLM, S, 2);
            S += __shfl_xor_sync(FULLM, S, 4);
            S += __shfl_xor_sync(FULLM, S, 8);
            float Sinv = 1.f / fmaxf(S, 1e-30f);
            float S2 = 0.f;
            #pragma unroll
            for (int q = 0; q < NQ; q++) {
                int e = j16 + q*16;
                if (e < cnt) {
                    float b = 0.5f * pv[q] * Sinv + 0.5f * ppr_sh[e];
                    float v2 = __expf(b);
                    pbuf[k16*PSTR + e] = v2;
                    S2 += v2;
                }
            }
            S2 += __shfl_xor_sync(FULLM, S2, 1);
            S2 += __shfl_xor_sync(FULLM, S2, 2);
            S2 += __shfl_xor_sync(FULLM, S2, 4);
            S2 += __shfl_xor_sync(FULLM, S2, 8);
            if (j16 == 0) ssv[k16] = 1.f / fmaxf(S2, 1e-30f);
            __syncthreads();                           // B2

            // ---- Pass B: register FMAs (pad edges: xv = 0) ----
            float4 acc = make_float4(0.f,0.f,0.f,0.f);
            #pragma unroll
            for (int i = 0; i < T4MAX; i++) {
                if (i < T4) {
                    int e = w + (i << 2);
                    float pw = pbuf[cgrp*PSTR + e];
                    acc.x += xv[i].x*pw; acc.y += xv[i].y*pw;
                    acc.z += xv[i].z*pw; acc.w += xv[i].w*pw;
                }
            }
            red4[t] = acc;
            __syncthreads();                           // B3

            float s2i = ssv[cgrp];
            float4 a0 = red4[l], a1 = red4[32+l], a2 = red4[64+l], a3 = red4[96+l];
            float4 un;
            un.x = (a0.x+a1.x+a2.x+a3.x) * s2i;
            un.y = (a0.y+a1.y+a2.y+a3.y) * s2i;
            un.z = (a0.z+a1.z+a2.z+a3.z) * s2i;
            un.w = (a0.w+a1.w+a2.w+a3.w) * s2i;

            if (it < 2) {
                float sq = un.x*un.x + un.y*un.y + un.z*un.z + un.w*un.w;
                sq += __shfl_xor_sync(FULLM, sq, 1);
                sq += __shfl_xor_sync(FULLM, sq, 2);
                float inv = 1.f / fmaxf(sqrtf(sq), 1e-12f);
                u4.x = un.x*inv; u4.y = un.y*inv; u4.z = un.z*inv; u4.w = un.w*inv;
            } else if (w == 0) {
                ((float4*)(out + (size_t)r * DIM))[l] = un;
            }
        }
    } else {
        // =================== FALLBACK PATH (~2% of rows) ===================
        float* pb_g = g_pbuf + (size_t)s * KC;   // [k*cnt + e]

        float4 u4 = make_float4(0.f,0.f,0.f,0.f);
        for (int e = w; e < cnt; e += 4) {
            float4 xv = ((const float4*)(g_xn + (size_t)colg[s+e]*DIM))[l];
            float pe = pprg[s + e];
            u4.x += xv.x*pe; u4.y += xv.y*pe; u4.z += xv.z*pe; u4.w += xv.w*pe;
        }
        red4[t] = u4;
        __syncthreads();
        {
            float4 a0 = red4[l], a1 = red4[32+l], a2 = red4[64+l], a3 = red4[96+l];
            u4.x = a0.x+a1.x+a2.x+a3.x; u4.y = a0.y+a1.y+a2.y+a3.y;
            u4.z = a0.z+a1.z+a2.z+a3.z; u4.w = a0.w+a1.w+a2.w+a3.w;
        }

        #pragma unroll
        for (int it = 0; it < 3; it++) {
            for (int e = w; e < cnt; e += 4) {
                float4 xv = ((const float4*)(g_xn + (size_t)colg[s+e]*DIM))[l];
                float d = u4.x*xv.x + u4.y*xv.y + u4.z*xv.z + u4.w*xv.w;
                d += __shfl_xor_sync(FULLM, d, 1);
                d += __shfl_xor_sync(FULLM, d, 2);
                if ((l & 3) == 0) pb_g[cgrp*cnt + e] = d;
            }
            __syncthreads();

            float m = -1e30f;
            for (int e = j16; e < cnt; e += 16)
                m = fmaxf(m, pb_g[k16*cnt + e]);
            m = fmaxf(m, __shfl_xor_sync(FULLM, m, 1));
            m = fmaxf(m, __shfl_xor_sync(FULLM, m, 2));
            m = fmaxf(m, __shfl_xor_sync(FULLM, m, 4));
            m = fmaxf(m, __shfl_xor_sync(FULLM, m, 8));
            float S = 0.f;
            for (int e = j16; e < cnt; e += 16) {
                float v = __expf(pb_g[k16*cnt + e] - m);
                pb_g[k16*cnt + e] = v; S += v;
            }
            S += __shfl_xor_sync(FULLM, S, 1);
            S += __shfl_xor_sync(FULLM, S, 2);
            S += __shfl_xor_sync(FULLM, S, 4);
            S += __shfl_xor_sync(FULLM, S, 8);
            float Sinv = 1.f / fmaxf(S, 1e-30f);
            float S2 = 0.f;
            for (int e = j16; e < cnt; e += 16) {
                float b = 0.5f * pb_g[k16*cnt + e] * Sinv + 0.5f * pprg[s + e];
                float v2 = __expf(b);
                pb_g[k16*cnt + e] = v2; S2 += v2;
            }
            S2 += __shfl_xor_sync(FULLM, S2, 1);
            S2 += __shfl_xor_sync(FULLM, S2, 2);
            S2 += __shfl_xor_sync(FULLM, S2, 4);
            S2 += __shfl_xor_sync(FULLM, S2, 8);
            if (j16 == 0) ssv[k16] = 1.f / fmaxf(S2, 1e-30f);
            __syncthreads();

            float4 acc = make_float4(0.f,0.f,0.f,0.f);
            for (int e = w; e < cnt; e += 4) {
                float4 xv = ((const float4*)(g_xn + (size_t)colg[s+e]*DIM))[l];
                float pw = pb_g[cgrp*cnt + e];
                acc.x += xv.x*pw; acc.y += xv.y*pw;
                acc.z += xv.z*pw; acc.w += xv.w*pw;
            }
            red4[t] = acc;
            __syncthreads();
            float s2i = ssv[cgrp];
            float4 a0 = red4[l], a1 = red4[32+l], a2 = red4[64+l], a3 = red4[96+l];
            float4 un;
            un.x = (a0.x+a1.x+a2.x+a3.x) * s2i;
            un.y = (a0.y+a1.y+a2.y+a3.y) * s2i;
            un.z = (a0.z+a1.z+a2.z+a3.z) * s2i;
            un.w = (a0.w+a1.w+a2.w+a3.w) * s2i;

            if (it < 2) {
                float sq = un.x*un.x + un.y*un.y + un.z*un.z + un.w*un.w;
                sq += __shfl_xor_sync(FULLM, sq, 1);
                sq += __shfl_xor_sync(FULLM, sq, 2);
                float inv = 1.f / fmaxf(sqrtf(sq), 1e-12f);
                u4.x = un.x*inv; u4.y = un.y*inv; u4.z = un.z*inv; u4.w = un.w*inv;
            } else if (w == 0) {
                ((float4*)(out + (size_t)r * DIM))[l] = un;
            }
            __syncthreads();   // pb_g reuse next iteration
        }
    }
}

// ---------------------------------------------------------------------------
extern "C" void kernel_launch(void* const* d_in, const int* in_sizes, int n_in,
                              void* d_out, int out_size)
{
    const float* x    = (const float*)d_in[0];
    const float* ppr  = (const float*)d_in[1];
    const int*   row  = (const int*)  d_in[2];
    const int*   col  = (const int*)  d_in[3];
    float* out = (float*)d_out;

    int n = in_sizes[0] / DIM;
    if (n > NMAX) n = NMAX;
    int E = in_sizes[1];
    if (E > EMAX) E = EMAX;
    if (n <= 0) return;

    const int ncap = n * KC;
    knorm<<<(ncap + 255) / 256, 256>>>(x, ncap);
    krows<<<(n + 1 + 255) / 256, 256>>>(row, n, E);

    // smem floats: pbuf 8*52 + ppr 44 + ssv 8 + red4 512  = 980 -> 3920 B
    const size_t SMEM = (size_t)(KC*PSTR + XCAP + KC + DIM*4) * sizeof(float);
    kmain<<<n, 128, SMEM>>>(ppr, col, out, E);
}